// round 16
// baseline (speedup 1.0000x reference)
#include <cuda_runtime.h>
#include <cuda_bf16.h>
#include <cstdint>

// ---------------- problem constants ----------------
#define LLEN   256
#define DDIM   1024
#define TOKENS 1024            // B*L
#define BLD    (1024*1024)     // TOKENS*D
#define XDB    (1024*96)       // TOKENS*96
#define LQN    77
#define MH     308             // B*LQ
#define MHP    384             // MH padded to 3*128
#define OUTF   768

// ---------------- scratch buffers (no runtime allocation allowed) ----------------
__device__ float g_res [BLD];
__device__ float g_h   [2*BLD];     // split-K partials h0 | h1
__device__ float g_hn  [BLD];
__device__ float g_xz  [4*BLD];     // [tok][4096]: dir0 x|z, dir1 x|z
__device__ float g_xc  [2*BLD];     // conv+silu output per dir
__device__ float g_dt  [2*BLD];
__device__ float g_xdbl[2*XDB];     // [dir][tok][96]
__device__ float g_yp  [2*BLD];     // [tok][2048]: dir0 | dir1
__device__ float g_kv  [2*BLD];     // [tok][2048]
__device__ float g_o   [MHP*1024];  // rows >= MH stay zero
__device__ float g_po  [MHP*1024];
__device__ float g_s1  [MHP*1536];

// ---------------- math helpers ----------------
__device__ __forceinline__ float siluf(float v){ return v / (1.f + __expf(-v)); }
__device__ __forceinline__ float softplusf(float v){ return v > 20.f ? v : log1pf(__expf(v)); }

// pack two floats to bf16x2: low half = lo arg, high half = hi arg
__device__ __forceinline__ uint32_t packbf(float lo, float hi){
    uint32_t r; asm("cvt.rn.bf16x2.f32 %0, %1, %2;" : "=r"(r) : "f"(hi), "f"(lo)); return r;
}
// split float4 -> {hi01, lo01, hi23, lo23} (hi = bf16 round, lo = bf16(residual))
__device__ __forceinline__ uint4 cvt_split(float4 v){
    uint32_t h01 = packbf(v.x, v.y);
    float rx = v.x - __uint_as_float(h01 << 16);
    float ry = v.y - __uint_as_float(h01 & 0xffff0000u);
    uint32_t l01 = packbf(rx, ry);
    uint32_t h23 = packbf(v.z, v.w);
    float rz = v.z - __uint_as_float(h23 << 16);
    float rw = v.w - __uint_as_float(h23 & 0xffff0000u);
    uint32_t l23 = packbf(rz, rw);
    return make_uint4(h01, l01, h23, l23);
}
__device__ __forceinline__ void mma16(float* d, uint32_t a0, uint32_t a1, uint32_t a2, uint32_t a3,
                                      uint32_t b0, uint32_t b1){
    asm volatile(
        "mma.sync.aligned.m16n8k16.row.col.f32.bf16.bf16.f32 "
        "{%0,%1,%2,%3}, {%4,%5,%6,%7}, {%8,%9}, {%0,%1,%2,%3};\n"
        : "+f"(d[0]), "+f"(d[1]), "+f"(d[2]), "+f"(d[3])
        : "r"(a0), "r"(a1), "r"(a2), "r"(a3), "r"(b0), "r"(b1));
}

__device__ __forceinline__ float block_sum(float v, float* red){
    #pragma unroll
    for (int o = 16; o; o >>= 1) v += __shfl_xor_sync(0xffffffffu, v, o);
    int w = threadIdx.x >> 5, ln = threadIdx.x & 31;
    if (ln == 0) red[w] = v;
    __syncthreads();
    float t = (threadIdx.x < 8) ? red[threadIdx.x] : 0.f;
    #pragma unroll
    for (int o = 4; o; o >>= 1) t += __shfl_xor_sync(0xffffffffu, t, o);
    if (threadIdx.x == 0) red[0] = t;
    __syncthreads();
    t = red[0];
    __syncthreads();
    return t;
}
__device__ __forceinline__ float block_max(float v, float* red){
    #pragma unroll
    for (int o = 16; o; o >>= 1) v = fmaxf(v, __shfl_xor_sync(0xffffffffu, v, o));
    int w = threadIdx.x >> 5, ln = threadIdx.x & 31;
    if (ln == 0) red[w] = v;
    __syncthreads();
    float t = (threadIdx.x < 8) ? red[threadIdx.x] : -3.0e38f;
    #pragma unroll
    for (int o = 4; o; o >>= 1) t = fmaxf(t, __shfl_xor_sync(0xffffffffu, t, o));
    if (threadIdx.x == 0) red[0] = t;
    __syncthreads();
    t = red[0];
    __syncthreads();
    return t;
}

// ======= bf16-split3 mma.sync GEMM, double-buffered: C = act(A[M,K] @ W[N,K]^T + bias) =======
// A = Ah + Al, W = Wh + Wl (bf16 hi + bf16 residual); C ~= Ah*Wh + Ah*Wl + Al*Wh (err ~1e-5).
// CTA 128x128, 8 warps (2m x 4n), warp tile 64x32, K chunks of 32 (2 x m16n8k16 x 3 terms).
// DOUBLE-BUFFERED dynamic smem (2 x 40KB): one __syncthreads per chunk; staging of chunk c+1
// (cvt+STS from prefetch regs) and the LDG of chunk c+2 overlap the MMA compute of chunk c.
// Per tile row: 16 k slots of (hi,lo) word pairs, row stride 40 words; fragment reads LDS.64.
// Requires M%128==0, K%32==0, rows 16B-aligned; N guarded via Nreal.
// blockIdx.z strides sA/sW/sB/sC. SPLIT: final (a|b) output epilogue with m<MH guard.
#define TBUF 10240   // words per buffer: As 5120 | Bs 5120
template<int DOBIAS, int ACT, int SPLIT>
__global__ void __launch_bounds__(256, 2) mgemm_k(
    const float* __restrict__ A, int lda, long long sA,
    const float* __restrict__ W, int ldw, long long sW,
    const float* __restrict__ bias, long long sB,
    float* __restrict__ C, int ldc, long long sC,
    int K, int Nreal)
{
    extern __shared__ __align__(16) uint32_t sm[];   // 2 * TBUF words = 80KB

    if (sA) A += (size_t)blockIdx.z * sA;
    if (sW) W += (size_t)blockIdx.z * sW;
    if (sC) C += (size_t)blockIdx.z * sC;
    if (DOBIAS && sB) bias += (size_t)blockIdx.z * sB;

    const int tid  = threadIdx.x;
    const int lane = tid & 31;
    const int wid  = tid >> 5;
    const int wm   = wid >> 2;         // 0..1
    const int wn   = wid & 3;          // 0..3
    const int bm   = blockIdx.y * 128;
    const int bn   = blockIdx.x * 128;
    const int r4   = lane >> 2;        // 0..7
    const int c4   = lane & 3;         // 0..3

    float d[4][4][4];
    #pragma unroll
    for (int mt = 0; mt < 4; ++mt)
        #pragma unroll
        for (int nt = 0; nt < 4; ++nt)
            #pragma unroll
            for (int e = 0; e < 4; ++e) d[mt][nt][e] = 0.f;

    // staging: thread owns row srow, k-half sf (16 k each), 4 float4 per tile
    const int srow = tid >> 1;
    const int sf   = tid & 1;
    const float* Ap = A + (size_t)(bm + srow) * lda + sf * 16;
    const int nrow  = bn + srow;
    const bool bok  = (nrow < Nreal);
    const float* Wp = W + (size_t)(bok ? nrow : 0) * ldw + sf * 16;
    const int stoff = srow * 40 + sf * 16;

    const int nch = K >> 5;
    float4 pa[4], pb[4];

    // ---- prologue: stage chunk 0, prefetch chunk 1 ----
    #pragma unroll
    for (int j = 0; j < 4; ++j) {
        pa[j] = *(const float4*)(Ap + j * 4);
        pb[j] = bok ? *(const float4*)(Wp + j * 4) : make_float4(0.f, 0.f, 0.f, 0.f);
    }
    #pragma unroll
    for (int j = 0; j < 4; ++j) {
        *(uint4*)(sm + stoff + j * 4)        = cvt_split(pa[j]);
        *(uint4*)(sm + 5120 + stoff + j * 4) = cvt_split(pb[j]);
    }
    if (nch > 1) {
        #pragma unroll
        for (int j = 0; j < 4; ++j) {
            pa[j] = *(const float4*)(Ap + 32 + j * 4);
            pb[j] = bok ? *(const float4*)(Wp + 32 + j * 4) : make_float4(0.f, 0.f, 0.f, 0.f);
        }
    }
    __syncthreads();

    for (int c = 0; c < nch; ++c) {
        const uint32_t* curA = sm + (c & 1) * TBUF;
        const uint32_t* curB = curA + 5120;

        // ---- stage chunk c+1 into the other buffer; prefetch chunk c+2 ----
        if (c + 1 < nch) {
            uint32_t* nA = sm + ((c + 1) & 1) * TBUF + stoff;
            #pragma unroll
            for (int j = 0; j < 4; ++j) {
                *(uint4*)(nA + j * 4)        = cvt_split(pa[j]);
                *(uint4*)(nA + 5120 + j * 4) = cvt_split(pb[j]);
            }
            if (c + 2 < nch) {
                int k0 = (c + 2) * 32;
                #pragma unroll
                for (int j = 0; j < 4; ++j) {
                    pa[j] = *(const float4*)(Ap + k0 + j * 4);
                    pb[j] = bok ? *(const float4*)(Wp + k0 + j * 4)
                                : make_float4(0.f, 0.f, 0.f, 0.f);
                }
            }
        }

        // ---- compute: 2 ksteps of m16n8k16 x 3 terms ----
        #pragma unroll
        for (int ks = 0; ks < 2; ++ks) {
            uint2 bf_[4][2];    // [nt][b0/b1], .x = hi, .y = lo
            #pragma unroll
            for (int nt = 0; nt < 4; ++nt) {
                const uint32_t* bp = curB + (wn * 32 + nt * 8 + r4) * 40 + (ks * 8 + c4) * 2;
                bf_[nt][0] = *(const uint2*)(bp);
                bf_[nt][1] = *(const uint2*)(bp + 8);
            }
            #pragma unroll
            for (int mt = 0; mt < 4; ++mt) {
                const uint32_t* ap0 = curA + (wm * 64 + mt * 16 + r4) * 40 + (ks * 8 + c4) * 2;
                const uint32_t* ap1 = ap0 + 8 * 40;
                uint2 a0 = *(const uint2*)(ap0);
                uint2 a1 = *(const uint2*)(ap1);
                uint2 a2 = *(const uint2*)(ap0 + 8);
                uint2 a3 = *(const uint2*)(ap1 + 8);
                #pragma unroll
                for (int nt = 0; nt < 4; ++nt) {
                    mma16(d[mt][nt], a0.x, a1.x, a2.x, a3.x, bf_[nt][0].x, bf_[nt][1].x); // Ah*Wh
                    mma16(d[mt][nt], a0.x, a1.x, a2.x, a3.x, bf_[nt][0].y, bf_[nt][1].y); // Ah*Wl
                    mma16(d[mt][nt], a0.y, a1.y, a2.y, a3.y, bf_[nt][0].x, bf_[nt][1].x); // Al*Wh
                }
            }
        }
        __syncthreads();
    }

    // ---- epilogue: c0/c1 at (row, col0/col0+1), c2/c3 at row+8 ----
    #pragma unroll
    for (int mt = 0; mt < 4; ++mt) {
        int row0 = bm + wm * 64 + mt * 16 + r4;
        #pragma unroll
        for (int nt = 0; nt < 4; ++nt) {
            int col0 = bn + wn * 32 + nt * 8 + c4 * 2;
            if (col0 >= Nreal) continue;
            float v0 = d[mt][nt][0], v1 = d[mt][nt][1];
            float v2 = d[mt][nt][2], v3 = d[mt][nt][3];
            if (DOBIAS) {
                float bz0 = bias[col0], bz1 = bias[col0 + 1];
                v0 += bz0; v1 += bz1; v2 += bz0; v3 += bz1;
            }
            if (ACT == 1)      { v0 = siluf(v0); v1 = siluf(v1); v2 = siluf(v2); v3 = siluf(v3); }
            else if (ACT == 2) { v0 = softplusf(v0); v1 = softplusf(v1);
                                 v2 = softplusf(v2); v3 = softplusf(v3); }
            if (SPLIT) {
                // out layout: a = s[:, :768] then b = s[:, 768:], each [MH][768]
                float* o0 = (col0 < OUTF)
                    ? (C + (size_t)row0 * OUTF + col0)
                    : (C + (size_t)MH * OUTF + (size_t)row0 * OUTF + (col0 - OUTF));
                if (row0 < MH)     *(float2*)o0 = make_float2(v0, v1);
                if (row0 + 8 < MH) *(float2*)(o0 + (size_t)8 * OUTF) = make_float2(v2, v3);
            } else {
                *(float2*)(C + (size_t)row0 * ldc + col0)       = make_float2(v0, v1);
                *(float2*)(C + (size_t)(row0 + 8) * ldc + col0) = make_float2(v2, v3);
            }
        }
    }
}

// ---------------- residual-add(s) + LayerNorm(*w) ----------------
__global__ void __launch_bounds__(256) ln_k(const float* __restrict__ add0,
                                            const float* __restrict__ add1,
                                            float* __restrict__ res,
                                            const float* __restrict__ w,
                                            float* __restrict__ out)
{
    __shared__ float red[8];
    int t = blockIdx.x;
    size_t base = (size_t)t * DDIM;
    int tid = threadIdx.x;
    float v[4];
    #pragma unroll
    for (int j = 0; j < 4; ++j) {
        int d = j * 256 + tid;
        float r = res[base + d];
        if (add0) { r += add0[base + d] + add1[base + d]; res[base + d] = r; }
        v[j] = r;
    }
    float s = v[0] + v[1] + v[2] + v[3];
    s = block_sum(s, red);
    float mean = s * (1.f / DDIM);
    float q = 0.f;
    #pragma unroll
    for (int j = 0; j < 4; ++j) { float d0 = v[j] - mean; q += d0 * d0; }
    q = block_sum(q, red);
    float inv = rsqrtf(q * (1.f / DDIM) + 1e-5f);
    #pragma unroll
    for (int j = 0; j < 4; ++j) {
        int d = j * 256 + tid;
        out[base + d] = (v[j] - mean) * inv * w[d];
    }
}

// ---------------- depthwise conv (dir0 causal, dir1 anti-causal) + bias + silu ----------------
__global__ void __launch_bounds__(256) conv_k(const float* __restrict__ cw,
                                              const float* __restrict__ cb,
                                              int layer)
{
    int g = blockIdx.x * 256 + threadIdx.x;
    int tok = g >> 10, d = g & 1023;
    int b = tok >> 8, t = tok & 255;
    const float* xz_b = g_xz + (size_t)b * 256 * 4096;
    {
        const float* w = cw + ((size_t)(layer * 2 + 0) * 1024 + d) * 4;
        float a = cb[(size_t)(layer * 2 + 0) * 1024 + d];
        #pragma unroll
        for (int j = 0; j < 4; ++j) {
            int ts = t - 3 + j;
            if (ts >= 0) a = fmaf(w[j], xz_b[(size_t)ts * 4096 + d], a);
        }
        g_xc[(size_t)tok * 1024 + d] = siluf(a);
    }
    {
        const float* w = cw + ((size_t)(layer * 2 + 1) * 1024 + d) * 4;
        float a = cb[(size_t)(layer * 2 + 1) * 1024 + d];
        #pragma unroll
        for (int j = 0; j < 4; ++j) {
            int ts = t + 3 - j;
            if (ts <= 255) a = fmaf(w[j], xz_b[(size_t)ts * 4096 + 2048 + d], a);
        }
        g_xc[(size_t)BLD + (size_t)tok * 1024 + d] = siluf(a);
    }
}

// ---------------- selective scan with next-step prefetch ----------------
__global__ void __launch_bounds__(64) scan_k(const float* __restrict__ A_log,
                                             const float* __restrict__ D_p,
                                             int layer)
{
    int dir = blockIdx.z, b = blockIdx.y;
    int d = blockIdx.x * 64 + threadIdx.x;
    size_t pbase = (size_t)((layer * 2 + dir) * 1024 + d);
    float Ar[16];
    const float* al = A_log + pbase * 16;
    #pragma unroll
    for (int n = 0; n < 16; ++n) Ar[n] = -__expf(al[n]);
    float Dp = D_p[pbase];
    float h[16];
    #pragma unroll
    for (int n = 0; n < 16; ++n) h[n] = 0.f;

    const float* dt_p = g_dt + (size_t)dir * BLD + (size_t)b * 256 * 1024 + d;
    const float* x_p  = g_xc + (size_t)dir * BLD + (size_t)b * 256 * 1024 + d;
    const float* z_p  = g_xz + (size_t)b * 256 * 4096 + dir * 2048 + 1024 + d;
    const float* bc   = g_xdbl + (size_t)dir * XDB + (size_t)b * 256 * 96;
    float* y_p = g_yp + (size_t)b * 256 * 2048 + dir * 1024 + d;

    int t   = dir ? 255 : 0;
    int stp = dir ? -1 : 1;

    float dt_c = dt_p[(size_t)t * 1024];
    float xv_c = x_p [(size_t)t * 1024];
    float zv_c = z_p [(size_t)t * 4096];
    float4 Bq[4], Cq[4];
    {
        const float4* xv4 = (const float4*)(bc + t * 96 + 64);
        #pragma unroll
        for (int qk = 0; qk < 4; ++qk) { Bq[qk] = xv4[qk]; Cq[qk] = xv4[qk + 4]; }
    }

    for (int s = 0; s < 256; ++s) {
        int tn = t + stp;
        float dt_nv = 0.f, xv_n = 0.f, zv_n = 0.f;
        float4 Bn[4], Cn[4];
        if (s < 255) {
            dt_nv = dt_p[(size_t)tn * 1024];
            xv_n  = x_p [(size_t)tn * 1024];
            zv_n  = z_p [(size_t)tn * 4096];
            const float4* xv4 = (const float4*)(bc + tn * 96 + 64);
            #pragma unroll
            for (int qk = 0; qk < 4; ++qk) { Bn[qk] = xv4[qk]; Cn[qk] = xv4[qk + 4]; }
        }

        float Bf[16], Cf[16];
        #pragma unroll
        for (int qk = 0; qk < 4; ++qk) {
            Bf[qk*4+0] = Bq[qk].x; Bf[qk*4+1] = Bq[qk].y; Bf[qk*4+2] = Bq[qk].z; Bf[qk*4+3] = Bq[qk].w;
            Cf[qk*4+0] = Cq[qk].x; Cf[qk*4+1] = Cq[qk].y; Cf[qk*4+2] = Cq[qk].z; Cf[qk*4+3] = Cq[qk].w;
        }

        float dx = dt_c * xv_c;
        float y = 0.f;
        #pragma unroll
        for (int n = 0; n < 16; ++n) {
            float wv = __expf(dt_c * Ar[n]);
            h[n] = fmaf(wv, h[n], dx * Bf[n]);
            y = fmaf(h[n], Cf[n], y);
        }
        y = fmaf(xv_c, Dp, y);
        y_p[(size_t)t * 2048] = y * siluf(zv_c);

        t = tn; dt_c = dt_nv; xv_c = xv_n; zv_c = zv_n;
        #pragma unroll
        for (int qk = 0; qk < 4; ++qk) { Bq[qk] = Bn[qk]; Cq[qk] = Cn[qk]; }
    }
}

// ---------------- cross-attention: one block per (qi, head, batch) ----------------
__global__ void __launch_bounds__(256) attn_k(const float* __restrict__ q)
{
    __shared__ float qs[64];
    __shared__ float sc[256];
    __shared__ float po[4][64];
    __shared__ float red[8];
    int qi = blockIdx.x, hh = blockIdx.y, b = blockIdx.z;
    int tid = threadIdx.x;
    if (tid < 64) qs[tid] = q[((size_t)hh * LQN + qi) * 64 + tid];
    __syncthreads();
    float s;
    {
        const float* kp = g_kv + ((size_t)(b * 256 + tid)) * 2048 + hh * 128;
        float a = 0.f;
        #pragma unroll 8
        for (int d0 = 0; d0 < 64; ++d0) a = fmaf(qs[d0], kp[d0], a);
        s = a * 0.125f;
    }
    float mx = block_max(s, red);
    float e  = __expf(s - mx);
    float Z  = block_sum(e, red);
    sc[tid] = e / Z;
    __syncthreads();
    int d0 = tid & 63, tq = tid >> 6;
    float a = 0.f;
    const float* vb = g_kv + ((size_t)(b * 256 + tq * 64)) * 2048 + hh * 128 + 64 + d0;
    for (int tt = 0; tt < 64; ++tt) a = fmaf(sc[tq * 64 + tt], vb[(size_t)tt * 2048], a);
    po[tq][d0] = a;
    __syncthreads();
    if (tid < 64) {
        float o = po[0][tid] + po[1][tid] + po[2][tid] + po[3][tid];
        g_o[((size_t)b * LQN + qi) * 1024 + hh * 64 + tid] = o;
    }
}

// ---------------- host-side launch helper ----------------
#define MG_SMEM (2 * TBUF * 4)   // 80KB

template<int DOBIAS, int ACT, int SPLIT>
static void mg(const float* A, int lda, long long sA,
               const float* W, int ldw, long long sW,
               const float* bias, long long sB,
               float* C, int ldc, long long sC,
               int M, int Nreal, int Npad, int K, int nz)
{
    cudaFuncSetAttribute(mgemm_k<DOBIAS, ACT, SPLIT>,
                         cudaFuncAttributeMaxDynamicSharedMemorySize, MG_SMEM);
    dim3 grid(Npad / 128, M / 128, nz);
    mgemm_k<DOBIAS, ACT, SPLIT><<<grid, 256, MG_SMEM>>>(A, lda, sA, W, ldw, sW, bias, sB,
                                                        C, ldc, sC, K, Nreal);
}

extern "C" void kernel_launch(void* const* d_in, const int* in_sizes, int n_in,
                              void* d_out, int out_size)
{
    (void)in_sizes; (void)n_in; (void)out_size;
    const float* x       = (const float*)d_in[0];
    const float* stem_W  = (const float*)d_in[1];
    const float* stem_b  = (const float*)d_in[2];
    const float* norm_w  = (const float*)d_in[3];
    const float* in_W    = (const float*)d_in[4];
    const float* conv_w  = (const float*)d_in[5];
    const float* conv_b  = (const float*)d_in[6];
    const float* xproj_W = (const float*)d_in[7];
    const float* dt_W    = (const float*)d_in[8];
    const float* dt_b    = (const float*)d_in[9];
    const float* A_log   = (const float*)d_in[10];
    const float* D_p     = (const float*)d_in[11];
    const float* out_W   = (const float*)d_in[12];
    const float* q       = (const float*)d_in[13];
    const float* kv_W    = (const float*)d_in[14];
    const float* po_W    = (const float*)d_in[15];
    const float* po_b    = (const float*)d_in[16];
    const float* h1_W    = (const float*)d_in[17];
    const float* h1_b    = (const float*)d_in[18];
    const float* h2_W    = (const float*)d_in[19];
    const float* h2_b    = (const float*)d_in[20];
    float* out = (float*)d_out;

    float *p_res, *p_h, *p_hn, *p_xz, *p_xc, *p_dt, *p_xdbl, *p_yp, *p_kv, *p_o, *p_po, *p_s1;
    cudaGetSymbolAddress((void**)&p_res,  g_res);
    cudaGetSymbolAddress((void**)&p_h,    g_h);
    cudaGetSymbolAddress((void**)&p_hn,   g_hn);
    cudaGetSymbolAddress((void**)&p_xz,   g_xz);
    cudaGetSymbolAddress((void**)&p_xc,   g_xc);
    cudaGetSymbolAddress((void**)&p_dt,   g_dt);
    cudaGetSymbolAddress((void**)&p_xdbl, g_xdbl);
    cudaGetSymbolAddress((void**)&p_yp,   g_yp);
    cudaGetSymbolAddress((void**)&p_kv,   g_kv);
    cudaGetSymbolAddress((void**)&p_o,    g_o);
    cudaGetSymbolAddress((void**)&p_po,   g_po);
    cudaGetSymbolAddress((void**)&p_s1,   g_s1);

    // stem: res = x @ stem_W^T + stem_b   (M=1024, N=1024, K=64)
    mg<1,0,0>(x, 64, 0, stem_W, 64, 0, stem_b, 0,
              p_res, 1024, 0, TOKENS, 1024, 1024, 64, 1);

    for (int i = 0; i < 16; ++i) {
        // res += h0 + h1 (i>0); hn = LN(res)*norm_w[i]
        ln_k<<<TOKENS, 256>>>(i == 0 ? nullptr : p_h,
                              i == 0 ? nullptr : p_h + BLD,
                              p_res, norm_w + (size_t)i * 1024, p_hn);
        // xz (both dirs fused): N=4096, K=1024
        mg<0,0,0>(p_hn, 1024, 0, in_W + (size_t)i * 4096 * 1024, 1024, 0,
                  nullptr, 0, p_xz, 4096, 0, TOKENS, 4096, 4096, 1024, 1);
        // depthwise conv + silu (both dirs)
        conv_k<<<4096, 256>>>(conv_w, conv_b, i);
        // xproj: N=96 (padded to 128 with guards), dirs via z
        mg<0,0,0>(p_xc, 1024, BLD,
                  xproj_W + (size_t)i * 2 * 96 * 1024, 1024, (long long)96 * 1024,
                  nullptr, 0, p_xdbl, 96, XDB, TOKENS, 96, 128, 1024, 2);
        // dt = softplus(xdbl[:, :64] @ dt_W^T + dt_b): N=1024, K=64, dirs via z
        mg<1,2,0>(p_xdbl, 96, XDB,
                  dt_W + (size_t)i * 2 * 1024 * 64, 64, (long long)1024 * 64,
                  dt_b + (size_t)i * 2 * 1024, 1024,
                  p_dt, 1024, BLD, TOKENS, 1024, 1024, 64, 2);
        // selective scan (+x*Dp, *silu(z)) -> interleaved yp
        scan_k<<<dim3(16, 4, 2), 64>>>(A_log, D_p, i);
        // h0/h1 = yp[:, dir*1024:] @ out_W[i,dir]^T (split-K over dirs via z)
        mg<0,0,0>(p_yp, 2048, 1024,
                  out_W + (size_t)i * 2 * 1024 * 1024, 1024, (long long)1024 * 1024,
                  nullptr, 0, p_h, 1024, BLD, TOKENS, 1024, 1024, 1024, 2);
    }

    // final residual + LN
    ln_k<<<TOKENS, 256>>>(p_h, p_h + BLD, p_res, norm_w + (size_t)16 * 1024, p_hn);
    // kv projection: N=2048, K=1024
    mg<0,0,0>(p_hn, 1024, 0, kv_W, 1024, 0, nullptr, 0,
              p_kv, 2048, 0, TOKENS, 2048, 2048, 1024, 1);
    // attention
    attn_k<<<dim3(LQN, 16, 4), 256>>>(q);
    // s = silu(o @ po_W^T + po_b)   (M padded to 384; pad rows deterministic)
    mg<1,1,0>(p_o, 1024, 0, po_W, 1024, 0, po_b, 0,
              p_po, 1024, 0, MHP, 1024, 1024, 1024, 1);
    // s1 = silu(s @ h1_W^T + h1_b)
    mg<1,1,0>(p_po, 1024, 0, h1_W, 1024, 0, h1_b, 0,
              p_s1, 1536, 0, MHP, 1536, 1536, 1024, 1);
    // s2 = s1 @ h2_W^T + h2_b, split-written as (a | b) into d_out (m<308 guarded)
    mg<1,0,1>(p_s1, 1536, 0, h2_W, 1536, 0, h2_b, 0,
              out, 0, 0, MHP, 1536, 1536, 1536, 1);
}

// round 17
// speedup vs baseline: 1.1262x; 1.1262x over previous
#include <cuda_runtime.h>
#include <cuda_bf16.h>
#include <cstdint>

// ---------------- problem constants ----------------
#define LLEN   256
#define DDIM   1024
#define TOKENS 1024            // B*L
#define BLD    (1024*1024)     // TOKENS*D
#define XDB    (1024*96)       // TOKENS*96
#define LQN    77
#define MH     308             // B*LQ
#define MHP    384             // MH padded to 6*64
#define OUTF   768

// ---------------- scratch buffers (no runtime allocation allowed) ----------------
__device__ float g_res [BLD];
__device__ float g_h   [2*BLD];     // split-K partials h0 | h1
__device__ float g_hn  [BLD];
__device__ float g_xz  [4*BLD];     // [tok][4096]: dir0 x|z, dir1 x|z
__device__ float g_xc  [2*BLD];     // conv+silu output per dir
__device__ float g_dt  [2*BLD];
__device__ float g_xdbl[2*XDB];     // [dir][tok][96]
__device__ float g_yp  [2*BLD];     // [tok][2048]: dir0 | dir1
__device__ float g_kv  [2*BLD];     // [tok][2048]
__device__ float g_o   [MHP*1024];  // rows >= MH stay zero
__device__ float g_po  [MHP*1024];
__device__ float g_s1  [MHP*1536];

// ---------------- math helpers ----------------
__device__ __forceinline__ float siluf(float v){ return v / (1.f + __expf(-v)); }
__device__ __forceinline__ float softplusf(float v){ return v > 20.f ? v : log1pf(__expf(v)); }

// pack two floats to bf16x2: low half = lo arg, high half = hi arg
__device__ __forceinline__ uint32_t packbf(float lo, float hi){
    uint32_t r; asm("cvt.rn.bf16x2.f32 %0, %1, %2;" : "=r"(r) : "f"(hi), "f"(lo)); return r;
}
// split float4 -> {hi01, lo01, hi23, lo23} (hi = bf16 round, lo = bf16(residual))
__device__ __forceinline__ uint4 cvt_split(float4 v){
    uint32_t h01 = packbf(v.x, v.y);
    float rx = v.x - __uint_as_float(h01 << 16);
    float ry = v.y - __uint_as_float(h01 & 0xffff0000u);
    uint32_t l01 = packbf(rx, ry);
    uint32_t h23 = packbf(v.z, v.w);
    float rz = v.z - __uint_as_float(h23 << 16);
    float rw = v.w - __uint_as_float(h23 & 0xffff0000u);
    uint32_t l23 = packbf(rz, rw);
    return make_uint4(h01, l01, h23, l23);
}
__device__ __forceinline__ void mma16(float* d, uint32_t a0, uint32_t a1, uint32_t a2, uint32_t a3,
                                      uint32_t b0, uint32_t b1){
    asm volatile(
        "mma.sync.aligned.m16n8k16.row.col.f32.bf16.bf16.f32 "
        "{%0,%1,%2,%3}, {%4,%5,%6,%7}, {%8,%9}, {%0,%1,%2,%3};\n"
        : "+f"(d[0]), "+f"(d[1]), "+f"(d[2]), "+f"(d[3])
        : "r"(a0), "r"(a1), "r"(a2), "r"(a3), "r"(b0), "r"(b1));
}

__device__ __forceinline__ float block_sum(float v, float* red){
    #pragma unroll
    for (int o = 16; o; o >>= 1) v += __shfl_xor_sync(0xffffffffu, v, o);
    int w = threadIdx.x >> 5, ln = threadIdx.x & 31;
    if (ln == 0) red[w] = v;
    __syncthreads();
    float t = (threadIdx.x < 8) ? red[threadIdx.x] : 0.f;
    #pragma unroll
    for (int o = 4; o; o >>= 1) t += __shfl_xor_sync(0xffffffffu, t, o);
    if (threadIdx.x == 0) red[0] = t;
    __syncthreads();
    t = red[0];
    __syncthreads();
    return t;
}
__device__ __forceinline__ float block_max(float v, float* red){
    #pragma unroll
    for (int o = 16; o; o >>= 1) v = fmaxf(v, __shfl_xor_sync(0xffffffffu, v, o));
    int w = threadIdx.x >> 5, ln = threadIdx.x & 31;
    if (ln == 0) red[w] = v;
    __syncthreads();
    float t = (threadIdx.x < 8) ? red[threadIdx.x] : -3.0e38f;
    #pragma unroll
    for (int o = 4; o; o >>= 1) t = fmaxf(t, __shfl_xor_sync(0xffffffffu, t, o));
    if (threadIdx.x == 0) red[0] = t;
    __syncthreads();
    t = red[0];
    __syncthreads();
    return t;
}

// ======= bf16-split3 mma.sync GEMM, 64x64 tile / high occupancy =======
// C = act(A[M,K] @ W[N,K]^T + bias); A = Ah+Al, W = Wh+Wl (bf16 hi + bf16 residual);
// C ~= Ah*Wh + Ah*Wl + Al*Wh (err ~1e-5).
// CTA 64x64, 128 threads (4 warps: 2m x 2n), warp tile 32x32 (2 x m16n8k16 m-tiles,
// 4 n-tiles), K chunks of 32 (2 ksteps x 3 terms). Single 20KB smem buffer,
// __launch_bounds__(128,6) -> target 6 CTAs / 24 warps per SM for latency hiding.
// Smem rows: 16 (hi,lo) word pairs per 32-k, row stride 40 words; fragment reads LDS.64,
// provably bank-conflict-free. Requires M%64==0, K%32==0, rows 16B-aligned; N guarded
// via Nreal (grid padded to 64). blockIdx.z strides sA/sW/sB/sC.
// SPLIT: final (a|b) output epilogue with m<MH guard (OUTF%64==0 so no tile straddles).
template<int DOBIAS, int ACT, int SPLIT>
__global__ void __launch_bounds__(128, 6) mgemm_k(
    const float* __restrict__ A, int lda, long long sA,
    const float* __restrict__ W, int ldw, long long sW,
    const float* __restrict__ bias, long long sB,
    float* __restrict__ C, int ldc, long long sC,
    int K, int Nreal)
{
    __shared__ __align__(16) uint32_t As[64 * 40];   // 2560 words
    __shared__ __align__(16) uint32_t Bs[64 * 40];

    if (sA) A += (size_t)blockIdx.z * sA;
    if (sW) W += (size_t)blockIdx.z * sW;
    if (sC) C += (size_t)blockIdx.z * sC;
    if (DOBIAS && sB) bias += (size_t)blockIdx.z * sB;

    const int tid  = threadIdx.x;
    const int lane = tid & 31;
    const int wid  = tid >> 5;         // 0..3
    const int wm   = wid >> 1;         // 0..1
    const int wn   = wid & 1;          // 0..1
    const int bm   = blockIdx.y * 64;
    const int bn   = blockIdx.x * 64;
    const int r4   = lane >> 2;        // 0..7
    const int c4   = lane & 3;         // 0..3

    float d[2][4][4];
    #pragma unroll
    for (int mt = 0; mt < 2; ++mt)
        #pragma unroll
        for (int nt = 0; nt < 4; ++nt)
            #pragma unroll
            for (int e = 0; e < 4; ++e) d[mt][nt][e] = 0.f;

    // staging: thread owns row srow (0..63), k-half sf (16 k each), 4 float4 per tile
    const int srow = tid >> 1;
    const int sf   = tid & 1;
    const float* Ap = A + (size_t)(bm + srow) * lda + sf * 16;
    const int nrow  = bn + srow;
    const bool bok  = (nrow < Nreal);
    const float* Wp = W + (size_t)(bok ? nrow : 0) * ldw + sf * 16;
    const int stoff = srow * 40 + sf * 16;

    const int nch = K >> 5;
    for (int c = 0; c < nch; ++c) {
        const int k0 = c * 32;
        // ---- stage A then B (transient regs; ptxas interleaves under the reg cap) ----
        {
            float4 t0 = *(const float4*)(Ap + k0 + 0);
            float4 t1 = *(const float4*)(Ap + k0 + 4);
            float4 t2 = *(const float4*)(Ap + k0 + 8);
            float4 t3 = *(const float4*)(Ap + k0 + 12);
            *(uint4*)(As + stoff + 0)  = cvt_split(t0);
            *(uint4*)(As + stoff + 4)  = cvt_split(t1);
            *(uint4*)(As + stoff + 8)  = cvt_split(t2);
            *(uint4*)(As + stoff + 12) = cvt_split(t3);
        }
        {
            float4 z = make_float4(0.f, 0.f, 0.f, 0.f);
            float4 u0 = bok ? *(const float4*)(Wp + k0 + 0)  : z;
            float4 u1 = bok ? *(const float4*)(Wp + k0 + 4)  : z;
            float4 u2 = bok ? *(const float4*)(Wp + k0 + 8)  : z;
            float4 u3 = bok ? *(const float4*)(Wp + k0 + 12) : z;
            *(uint4*)(Bs + stoff + 0)  = cvt_split(u0);
            *(uint4*)(Bs + stoff + 4)  = cvt_split(u1);
            *(uint4*)(Bs + stoff + 8)  = cvt_split(u2);
            *(uint4*)(Bs + stoff + 12) = cvt_split(u3);
        }
        __syncthreads();

        // ---- compute: 2 ksteps of m16n8k16 x 3 terms ----
        #pragma unroll
        for (int ks = 0; ks < 2; ++ks) {
            uint2 bf_[4][2];    // [nt][b0/b1], .x = hi, .y = lo
            #pragma unroll
            for (int nt = 0; nt < 4; ++nt) {
                const uint32_t* bp = Bs + (wn * 32 + nt * 8 + r4) * 40 + (ks * 8 + c4) * 2;
                bf_[nt][0] = *(const uint2*)(bp);
                bf_[nt][1] = *(const uint2*)(bp + 8);
            }
            #pragma unroll
            for (int mt = 0; mt < 2; ++mt) {
                const uint32_t* ap0 = As + (wm * 32 + mt * 16 + r4) * 40 + (ks * 8 + c4) * 2;
                const uint32_t* ap1 = ap0 + 8 * 40;
                uint2 a0 = *(const uint2*)(ap0);
                uint2 a1 = *(const uint2*)(ap1);
                uint2 a2 = *(const uint2*)(ap0 + 8);
                uint2 a3 = *(const uint2*)(ap1 + 8);
                #pragma unroll
                for (int nt = 0; nt < 4; ++nt) {
                    mma16(d[mt][nt], a0.x, a1.x, a2.x, a3.x, bf_[nt][0].x, bf_[nt][1].x); // Ah*Wh
                    mma16(d[mt][nt], a0.x, a1.x, a2.x, a3.x, bf_[nt][0].y, bf_[nt][1].y); // Ah*Wl
                    mma16(d[mt][nt], a0.y, a1.y, a2.y, a3.y, bf_[nt][0].x, bf_[nt][1].x); // Al*Wh
                }
            }
        }
        __syncthreads();
    }

    // ---- epilogue: c0/c1 at (row0, col0/col0+1), c2/c3 at row0+8 ----
    #pragma unroll
    for (int mt = 0; mt < 2; ++mt) {
        int row0 = bm + wm * 32 + mt * 16 + r4;
        #pragma unroll
        for (int nt = 0; nt < 4; ++nt) {
            int col0 = bn + wn * 32 + nt * 8 + c4 * 2;
            if (col0 >= Nreal) continue;
            float v0 = d[mt][nt][0], v1 = d[mt][nt][1];
            float v2 = d[mt][nt][2], v3 = d[mt][nt][3];
            if (DOBIAS) {
                float bz0 = bias[col0], bz1 = bias[col0 + 1];
                v0 += bz0; v1 += bz1; v2 += bz0; v3 += bz1;
            }
            if (ACT == 1)      { v0 = siluf(v0); v1 = siluf(v1); v2 = siluf(v2); v3 = siluf(v3); }
            else if (ACT == 2) { v0 = softplusf(v0); v1 = softplusf(v1);
                                 v2 = softplusf(v2); v3 = softplusf(v3); }
            if (SPLIT) {
                // out layout: a = s[:, :768] then b = s[:, 768:], each [MH][768]
                float* o0 = (col0 < OUTF)
                    ? (C + (size_t)row0 * OUTF + col0)
                    : (C + (size_t)MH * OUTF + (size_t)row0 * OUTF + (col0 - OUTF));
                if (row0 < MH)     *(float2*)o0 = make_float2(v0, v1);
                if (row0 + 8 < MH) *(float2*)(o0 + (size_t)8 * OUTF) = make_float2(v2, v3);
            } else {
                *(float2*)(C + (size_t)row0 * ldc + col0)       = make_float2(v0, v1);
                *(float2*)(C + (size_t)(row0 + 8) * ldc + col0) = make_float2(v2, v3);
            }
        }
    }
}

// ---------------- residual-add(s) + LayerNorm(*w) ----------------
__global__ void __launch_bounds__(256) ln_k(const float* __restrict__ add0,
                                            const float* __restrict__ add1,
                                            float* __restrict__ res,
                                            const float* __restrict__ w,
                                            float* __restrict__ out)
{
    __shared__ float red[8];
    int t = blockIdx.x;
    size_t base = (size_t)t * DDIM;
    int tid = threadIdx.x;
    float v[4];
    #pragma unroll
    for (int j = 0; j < 4; ++j) {
        int d = j * 256 + tid;
        float r = res[base + d];
        if (add0) { r += add0[base + d] + add1[base + d]; res[base + d] = r; }
        v[j] = r;
    }
    float s = v[0] + v[1] + v[2] + v[3];
    s = block_sum(s, red);
    float mean = s * (1.f / DDIM);
    float q = 0.f;
    #pragma unroll
    for (int j = 0; j < 4; ++j) { float d0 = v[j] - mean; q += d0 * d0; }
    q = block_sum(q, red);
    float inv = rsqrtf(q * (1.f / DDIM) + 1e-5f);
    #pragma unroll
    for (int j = 0; j < 4; ++j) {
        int d = j * 256 + tid;
        out[base + d] = (v[j] - mean) * inv * w[d];
    }
}

// ---------------- depthwise conv (dir0 causal, dir1 anti-causal) + bias + silu ----------------
__global__ void __launch_bounds__(256) conv_k(const float* __restrict__ cw,
                                              const float* __restrict__ cb,
                                              int layer)
{
    int g = blockIdx.x * 256 + threadIdx.x;
    int tok = g >> 10, d = g & 1023;
    int b = tok >> 8, t = tok & 255;
    const float* xz_b = g_xz + (size_t)b * 256 * 4096;
    {
        const float* w = cw + ((size_t)(layer * 2 + 0) * 1024 + d) * 4;
        float a = cb[(size_t)(layer * 2 + 0) * 1024 + d];
        #pragma unroll
        for (int j = 0; j < 4; ++j) {
            int ts = t - 3 + j;
            if (ts >= 0) a = fmaf(w[j], xz_b[(size_t)ts * 4096 + d], a);
        }
        g_xc[(size_t)tok * 1024 + d] = siluf(a);
    }
    {
        const float* w = cw + ((size_t)(layer * 2 + 1) * 1024 + d) * 4;
        float a = cb[(size_t)(layer * 2 + 1) * 1024 + d];
        #pragma unroll
        for (int j = 0; j < 4; ++j) {
            int ts = t + 3 - j;
            if (ts <= 255) a = fmaf(w[j], xz_b[(size_t)ts * 4096 + 2048 + d], a);
        }
        g_xc[(size_t)BLD + (size_t)tok * 1024 + d] = siluf(a);
    }
}

// ---------------- selective scan with next-step prefetch ----------------
__global__ void __launch_bounds__(64) scan_k(const float* __restrict__ A_log,
                                             const float* __restrict__ D_p,
                                             int layer)
{
    int dir = blockIdx.z, b = blockIdx.y;
    int d = blockIdx.x * 64 + threadIdx.x;
    size_t pbase = (size_t)((layer * 2 + dir) * 1024 + d);
    float Ar[16];
    const float* al = A_log + pbase * 16;
    #pragma unroll
    for (int n = 0; n < 16; ++n) Ar[n] = -__expf(al[n]);
    float Dp = D_p[pbase];
    float h[16];
    #pragma unroll
    for (int n = 0; n < 16; ++n) h[n] = 0.f;

    const float* dt_p = g_dt + (size_t)dir * BLD + (size_t)b * 256 * 1024 + d;
    const float* x_p  = g_xc + (size_t)dir * BLD + (size_t)b * 256 * 1024 + d;
    const float* z_p  = g_xz + (size_t)b * 256 * 4096 + dir * 2048 + 1024 + d;
    const float* bc   = g_xdbl + (size_t)dir * XDB + (size_t)b * 256 * 96;
    float* y_p = g_yp + (size_t)b * 256 * 2048 + dir * 1024 + d;

    int t   = dir ? 255 : 0;
    int stp = dir ? -1 : 1;

    float dt_c = dt_p[(size_t)t * 1024];
    float xv_c = x_p [(size_t)t * 1024];
    float zv_c = z_p [(size_t)t * 4096];
    float4 Bq[4], Cq[4];
    {
        const float4* xv4 = (const float4*)(bc + t * 96 + 64);
        #pragma unroll
        for (int qk = 0; qk < 4; ++qk) { Bq[qk] = xv4[qk]; Cq[qk] = xv4[qk + 4]; }
    }

    for (int s = 0; s < 256; ++s) {
        int tn = t + stp;
        float dt_nv = 0.f, xv_n = 0.f, zv_n = 0.f;
        float4 Bn[4], Cn[4];
        if (s < 255) {
            dt_nv = dt_p[(size_t)tn * 1024];
            xv_n  = x_p [(size_t)tn * 1024];
            zv_n  = z_p [(size_t)tn * 4096];
            const float4* xv4 = (const float4*)(bc + tn * 96 + 64);
            #pragma unroll
            for (int qk = 0; qk < 4; ++qk) { Bn[qk] = xv4[qk]; Cn[qk] = xv4[qk + 4]; }
        }

        float Bf[16], Cf[16];
        #pragma unroll
        for (int qk = 0; qk < 4; ++qk) {
            Bf[qk*4+0] = Bq[qk].x; Bf[qk*4+1] = Bq[qk].y; Bf[qk*4+2] = Bq[qk].z; Bf[qk*4+3] = Bq[qk].w;
            Cf[qk*4+0] = Cq[qk].x; Cf[qk*4+1] = Cq[qk].y; Cf[qk*4+2] = Cq[qk].z; Cf[qk*4+3] = Cq[qk].w;
        }

        float dx = dt_c * xv_c;
        float y = 0.f;
        #pragma unroll
        for (int n = 0; n < 16; ++n) {
            float wv = __expf(dt_c * Ar[n]);
            h[n] = fmaf(wv, h[n], dx * Bf[n]);
            y = fmaf(h[n], Cf[n], y);
        }
        y = fmaf(xv_c, Dp, y);
        y_p[(size_t)t * 2048] = y * siluf(zv_c);

        t = tn; dt_c = dt_nv; xv_c = xv_n; zv_c = zv_n;
        #pragma unroll
        for (int qk = 0; qk < 4; ++qk) { Bq[qk] = Bn[qk]; Cq[qk] = Cn[qk]; }
    }
}

// ---------------- cross-attention: one block per (qi, head, batch) ----------------
__global__ void __launch_bounds__(256) attn_k(const float* __restrict__ q)
{
    __shared__ float qs[64];
    __shared__ float sc[256];
    __shared__ float po[4][64];
    __shared__ float red[8];
    int qi = blockIdx.x, hh = blockIdx.y, b = blockIdx.z;
    int tid = threadIdx.x;
    if (tid < 64) qs[tid] = q[((size_t)hh * LQN + qi) * 64 + tid];
    __syncthreads();
    float s;
    {
        const float* kp = g_kv + ((size_t)(b * 256 + tid)) * 2048 + hh * 128;
        float a = 0.f;
        #pragma unroll 8
        for (int d0 = 0; d0 < 64; ++d0) a = fmaf(qs[d0], kp[d0], a);
        s = a * 0.125f;
    }
    float mx = block_max(s, red);
    float e  = __expf(s - mx);
    float Z  = block_sum(e, red);
    sc[tid] = e / Z;
    __syncthreads();
    int d0 = tid & 63, tq = tid >> 6;
    float a = 0.f;
    const float* vb = g_kv + ((size_t)(b * 256 + tq * 64)) * 2048 + hh * 128 + 64 + d0;
    for (int tt = 0; tt < 64; ++tt) a = fmaf(sc[tq * 64 + tt], vb[(size_t)tt * 2048], a);
    po[tq][d0] = a;
    __syncthreads();
    if (tid < 64) {
        float o = po[0][tid] + po[1][tid] + po[2][tid] + po[3][tid];
        g_o[((size_t)b * LQN + qi) * 1024 + hh * 64 + tid] = o;
    }
}

// ---------------- host-side launch helper ----------------
template<int DOBIAS, int ACT, int SPLIT>
static void mg(const float* A, int lda, long long sA,
               const float* W, int ldw, long long sW,
               const float* bias, long long sB,
               float* C, int ldc, long long sC,
               int M, int Nreal, int Npad, int K, int nz)
{
    dim3 grid(Npad / 64, M / 64, nz);
    mgemm_k<DOBIAS, ACT, SPLIT><<<grid, 128>>>(A, lda, sA, W, ldw, sW, bias, sB,
                                               C, ldc, sC, K, Nreal);
}

extern "C" void kernel_launch(void* const* d_in, const int* in_sizes, int n_in,
                              void* d_out, int out_size)
{
    (void)in_sizes; (void)n_in; (void)out_size;
    const float* x       = (const float*)d_in[0];
    const float* stem_W  = (const float*)d_in[1];
    const float* stem_b  = (const float*)d_in[2];
    const float* norm_w  = (const float*)d_in[3];
    const float* in_W    = (const float*)d_in[4];
    const float* conv_w  = (const float*)d_in[5];
    const float* conv_b  = (const float*)d_in[6];
    const float* xproj_W = (const float*)d_in[7];
    const float* dt_W    = (const float*)d_in[8];
    const float* dt_b    = (const float*)d_in[9];
    const float* A_log   = (const float*)d_in[10];
    const float* D_p     = (const float*)d_in[11];
    const float* out_W   = (const float*)d_in[12];
    const float* q       = (const float*)d_in[13];
    const float* kv_W    = (const float*)d_in[14];
    const float* po_W    = (const float*)d_in[15];
    const float* po_b    = (const float*)d_in[16];
    const float* h1_W    = (const float*)d_in[17];
    const float* h1_b    = (const float*)d_in[18];
    const float* h2_W    = (const float*)d_in[19];
    const float* h2_b    = (const float*)d_in[20];
    float* out = (float*)d_out;

    float *p_res, *p_h, *p_hn, *p_xz, *p_xc, *p_dt, *p_xdbl, *p_yp, *p_kv, *p_o, *p_po, *p_s1;
    cudaGetSymbolAddress((void**)&p_res,  g_res);
    cudaGetSymbolAddress((void**)&p_h,    g_h);
    cudaGetSymbolAddress((void**)&p_hn,   g_hn);
    cudaGetSymbolAddress((void**)&p_xz,   g_xz);
    cudaGetSymbolAddress((void**)&p_xc,   g_xc);
    cudaGetSymbolAddress((void**)&p_dt,   g_dt);
    cudaGetSymbolAddress((void**)&p_xdbl, g_xdbl);
    cudaGetSymbolAddress((void**)&p_yp,   g_yp);
    cudaGetSymbolAddress((void**)&p_kv,   g_kv);
    cudaGetSymbolAddress((void**)&p_o,    g_o);
    cudaGetSymbolAddress((void**)&p_po,   g_po);
    cudaGetSymbolAddress((void**)&p_s1,   g_s1);

    // stem: res = x @ stem_W^T + stem_b   (M=1024, N=1024, K=64)
    mg<1,0,0>(x, 64, 0, stem_W, 64, 0, stem_b, 0,
              p_res, 1024, 0, TOKENS, 1024, 1024, 64, 1);

    for (int i = 0; i < 16; ++i) {
        // res += h0 + h1 (i>0); hn = LN(res)*norm_w[i]
        ln_k<<<TOKENS, 256>>>(i == 0 ? nullptr : p_h,
                              i == 0 ? nullptr : p_h + BLD,
                              p_res, norm_w + (size_t)i * 1024, p_hn);
        // xz (both dirs fused): N=4096, K=1024
        mg<0,0,0>(p_hn, 1024, 0, in_W + (size_t)i * 4096 * 1024, 1024, 0,
                  nullptr, 0, p_xz, 4096, 0, TOKENS, 4096, 4096, 1024, 1);
        // depthwise conv + silu (both dirs)
        conv_k<<<4096, 256>>>(conv_w, conv_b, i);
        // xproj: N=96 (padded to 128 with guards), dirs via z
        mg<0,0,0>(p_xc, 1024, BLD,
                  xproj_W + (size_t)i * 2 * 96 * 1024, 1024, (long long)96 * 1024,
                  nullptr, 0, p_xdbl, 96, XDB, TOKENS, 96, 128, 1024, 2);
        // dt = softplus(xdbl[:, :64] @ dt_W^T + dt_b): N=1024, K=64, dirs via z
        mg<1,2,0>(p_xdbl, 96, XDB,
                  dt_W + (size_t)i * 2 * 1024 * 64, 64, (long long)1024 * 64,
                  dt_b + (size_t)i * 2 * 1024, 1024,
                  p_dt, 1024, BLD, TOKENS, 1024, 1024, 64, 2);
        // selective scan (+x*Dp, *silu(z)) -> interleaved yp
        scan_k<<<dim3(16, 4, 2), 64>>>(A_log, D_p, i);
        // h0/h1 = yp[:, dir*1024:] @ out_W[i,dir]^T (split-K over dirs via z)
        mg<0,0,0>(p_yp, 2048, 1024,
                  out_W + (size_t)i * 2 * 1024 * 1024, 1024, (long long)1024 * 1024,
                  nullptr, 0, p_h, 1024, BLD, TOKENS, 1024, 1024, 1024, 2);
    }

    // final residual + LN
    ln_k<<<TOKENS, 256>>>(p_h, p_h + BLD, p_res, norm_w + (size_t)16 * 1024, p_hn);
    // kv projection: N=2048, K=1024
    mg<0,0,0>(p_hn, 1024, 0, kv_W, 1024, 0, nullptr, 0,
              p_kv, 2048, 0, TOKENS, 2048, 2048, 1024, 1);
    // attention
    attn_k<<<dim3(LQN, 16, 4), 256>>>(q);
    // s = silu(o @ po_W^T + po_b)   (M padded to 384; pad rows deterministic)
    mg<1,1,0>(p_o, 1024, 0, po_W, 1024, 0, po_b, 0,
              p_po, 1024, 0, MHP, 1024, 1024, 1024, 1);
    // s1 = silu(s @ h1_W^T + h1_b)
    mg<1,1,0>(p_po, 1024, 0, h1_W, 1024, 0, h1_b, 0,
              p_s1, 1536, 0, MHP, 1536, 1536, 1024, 1);
    // s2 = s1 @ h2_W^T + h2_b, split-written as (a | b) into d_out (m<308 guarded)
    mg<1,0,1>(p_s1, 1536, 0, h2_W, 1536, 0, h2_b, 0,
              out, 0, 0, MHP, 1536, 1536, 1536, 1);
}